// round 12
// baseline (speedup 1.0000x reference)
#include <cuda_runtime.h>
#include <cuda_bf16.h>
#include <math.h>

#define B_   32
#define C_   512
#define HW_  1024
#define E_   256
#define A_   32
#define NC_  8
#define DC_  32
#define R_   24
#define PW_  256
#define P_   64

// ---------------- static device scratch ----------------
__device__ float d_G[B_ * C_ * C_];
__device__ float d_Z[3][B_ * C_ * P_];
__device__ float d_L[B_ * P_ * P_];
__device__ float d_T[B_ * P_ * P_];
__device__ float d_xmean[B_ * C_];
__device__ float d_an[A_ * E_];
__device__ float d_svdraw[B_ * R_];
__device__ float d_cw[B_ * C_];

// ---------------- helpers ----------------
__device__ __forceinline__ float blockReduceSum(float v, float* sh) {
    __syncthreads();
    int lane = threadIdx.x & 31, w = threadIdx.x >> 5;
#pragma unroll
    for (int o = 16; o; o >>= 1) v += __shfl_xor_sync(0xffffffffu, v, o);
    if (lane == 0) sh[w] = v;
    __syncthreads();
    int nw = blockDim.x >> 5;
    float r = (threadIdx.x < nw) ? sh[threadIdx.x] : 0.f;
    if (w == 0) {
#pragma unroll
        for (int o = 16; o; o >>= 1) r += __shfl_xor_sync(0xffffffffu, r, o);
        if (lane == 0) sh[0] = r;
    }
    __syncthreads();
    return sh[0];
}

__device__ __forceinline__ float gelu_f(float x) {
    return 0.5f * x * (1.f + erff(x * 0.70710678118654752f));
}
__device__ __forceinline__ float sigm_f(float x) { return 1.f / (1.f + expf(-x)); }

// ---------------- per-(b,c) spatial mean ----------------
__global__ void k_colmean(const float* __restrict__ x) {
    int bc = blockIdx.x;
    const float* p = x + (size_t)bc * HW_;
    float s = 0.f;
    for (int i = threadIdx.x; i < HW_; i += 256) s += p[i];
    __shared__ float red[32];
    s = blockReduceSum(s, red);
    if (threadIdx.x == 0) d_xmean[bc] = s * (1.f / HW_);
}

// ---------------- Gram: G[b] = X X^T / HW ----------------
__global__ void k_gram(const float* __restrict__ x) {
    int ti = blockIdx.x, tj = blockIdx.y, b = blockIdx.z;
    if (tj > ti) return;
    __shared__ float As[32][68];
    __shared__ float Bs[32][68];
    const float* X = x + (size_t)b * C_ * HW_;
    int t = threadIdx.x, tx = t & 15, ty = t >> 4, lk = t & 31, li = t >> 5;
    float acc[4][4] = {};
    for (int kk = 0; kk < HW_; kk += 32) {
#pragma unroll
        for (int m = 0; m < 8; m++) {
            int i = li + m * 8;
            As[lk][i] = X[(size_t)(ti * 64 + i) * HW_ + kk + lk];
            Bs[lk][i] = X[(size_t)(tj * 64 + i) * HW_ + kk + lk];
        }
        __syncthreads();
#pragma unroll 8
        for (int k = 0; k < 32; k++) {
            float a0[4], b0[4];
#pragma unroll
            for (int u = 0; u < 4; u++) { a0[u] = As[k][ty * 4 + u]; b0[u] = Bs[k][tx * 4 + u]; }
#pragma unroll
            for (int u = 0; u < 4; u++)
#pragma unroll
                for (int v = 0; v < 4; v++) acc[u][v] += a0[u] * b0[v];
        }
        __syncthreads();
    }
    float* G = d_G + (size_t)b * C_ * C_;
#pragma unroll
    for (int u = 0; u < 4; u++)
#pragma unroll
        for (int v = 0; v < 4; v++) {
            int gi = ti * 64 + ty * 4 + u, gj = tj * 64 + tx * 4 + v;
            float val = acc[u][v] * (1.f / HW_);
            G[gi * C_ + gj] = val;
            G[gj * C_ + gi] = val;
        }
}

// ---------------- deterministic pseudo-random init of Z0 ----------------
__global__ void k_initq() {
    int idx = blockIdx.x * 256 + threadIdx.x;
    unsigned int h = (unsigned int)idx * 2654435761u;
    h ^= h >> 16; h *= 2246822519u; h ^= h >> 13; h *= 3266489917u; h ^= h >> 16;
    d_Z[0][idx] = (float)(h & 0xFFFFFF) * (1.f / 8388608.f) - 1.f;
}

// ---------------- Zout = alpha*G*Zin + beta*Zin + gamma*Zprev ----------------
__global__ void k_gz(int zin, int zprev, int zout, float alpha, float beta, float gamma) {
    int rt = blockIdx.x, b = blockIdx.y;
    __shared__ float Gs[32][68];
    __shared__ float Zs[32][68];
    const float* G  = d_G + (size_t)b * C_ * C_;
    const float* Zi = d_Z[zin]  + (size_t)b * C_ * P_;
    const float* Zp = d_Z[zprev] + (size_t)b * C_ * P_;
    float*       Zo = d_Z[zout] + (size_t)b * C_ * P_;
    int t = threadIdx.x, tx = t & 15, ty = t >> 4, lk = t & 31, li = t >> 5;
    float acc[4][4] = {};
    for (int kk = 0; kk < C_; kk += 32) {
#pragma unroll
        for (int m = 0; m < 8; m++) {
            int i = li + m * 8;
            Gs[lk][i] = G[(size_t)(rt * 64 + i) * C_ + kk + lk];
        }
        {
            int j = t & 63, k0 = t >> 6;
#pragma unroll
            for (int m = 0; m < 8; m++) {
                int k = k0 * 8 + m;
                Zs[k][j] = Zi[(size_t)(kk + k) * P_ + j];
            }
        }
        __syncthreads();
#pragma unroll 8
        for (int k = 0; k < 32; k++) {
            float a0[4], b0[4];
#pragma unroll
            for (int u = 0; u < 4; u++) { a0[u] = Gs[k][ty * 4 + u]; b0[u] = Zs[k][tx * 4 + u]; }
#pragma unroll
            for (int u = 0; u < 4; u++)
#pragma unroll
                for (int v = 0; v < 4; v++) acc[u][v] += a0[u] * b0[v];
        }
        __syncthreads();
    }
#pragma unroll
    for (int u = 0; u < 4; u++)
#pragma unroll
        for (int v = 0; v < 4; v++) {
            int r = rt * 64 + ty * 4 + u, c = tx * 4 + v;
            Zo[(size_t)r * P_ + c] = alpha * acc[u][v] + beta * Zi[(size_t)r * P_ + c]
                                     + gamma * Zp[(size_t)r * P_ + c];
        }
}

// ---------------- S = Z^T Z (+ridge), Cholesky -> d_L ----------------
__global__ void k_syrk_chol(int zi) {
    int b = blockIdx.x, t = threadIdx.x;
    __shared__ float Zt[64][65];
    __shared__ float S[64][65];
    __shared__ float ridge;
    const float* Z = d_Z[zi] + (size_t)b * C_ * P_;
    int tx = t & 15, ty = t >> 4;
    float acc[4][4] = {};
    for (int kk = 0; kk < C_; kk += 64) {
        int j = t & 63, k0 = t >> 6;
#pragma unroll
        for (int m = 0; m < 16; m++) {
            int k = k0 * 16 + m;
            Zt[k][j] = Z[(size_t)(kk + k) * P_ + j];
        }
        __syncthreads();
#pragma unroll 8
        for (int k = 0; k < 64; k++) {
            float a0[4], b0[4];
#pragma unroll
            for (int u = 0; u < 4; u++) { a0[u] = Zt[k][ty * 4 + u]; b0[u] = Zt[k][tx * 4 + u]; }
#pragma unroll
            for (int u = 0; u < 4; u++)
#pragma unroll
                for (int v = 0; v < 4; v++) acc[u][v] += a0[u] * b0[v];
        }
        __syncthreads();
    }
#pragma unroll
    for (int u = 0; u < 4; u++)
#pragma unroll
        for (int v = 0; v < 4; v++) S[ty * 4 + u][tx * 4 + v] = acc[u][v];
    __syncthreads();
    if (t == 0) {
        float tr = 0.f;
        for (int i = 0; i < 64; i++) tr += S[i][i];
        ridge = 1e-6f * tr * (1.f / 64.f) + 1e-18f;
    }
    __syncthreads();
    if (t < 64) S[t][t] += ridge;
    __syncthreads();
    for (int k = 0; k < 64; k++) {
        if (t == 0) S[k][k] = sqrtf(fmaxf(S[k][k], 1e-20f));
        __syncthreads();
        float dk = S[k][k];
        for (int i = k + 1 + t; i < 64; i += 256) S[i][k] /= dk;
        __syncthreads();
        int rem = 63 - k;
        for (int idx = t; idx < rem * rem; idx += 256) {
            int i = k + 1 + idx / rem, j = k + 1 + idx % rem;
            S[i][j] -= S[i][k] * S[j][k];
        }
        __syncthreads();
    }
    for (int idx = t; idx < 4096; idx += 256) d_L[b * 4096 + idx] = S[idx >> 6][idx & 63];
}

// ---------------- Z <- Z * L^{-T} (row-wise forward substitution) ----------------
__global__ void __launch_bounds__(512) k_trsm(int zi) {
    int b = blockIdx.x, t = threadIdx.x;
    __shared__ float Ls[64][65];
    for (int idx = t; idx < 4096; idx += 512) Ls[idx >> 6][idx & 63] = d_L[b * 4096 + idx];
    __syncthreads();
    float* Zp = d_Z[zi] + ((size_t)b * C_ + t) * P_;
    float z[64];
#pragma unroll
    for (int j = 0; j < 16; j++) {
        float4 v = ((const float4*)Zp)[j];
        z[4 * j] = v.x; z[4 * j + 1] = v.y; z[4 * j + 2] = v.z; z[4 * j + 3] = v.w;
    }
#pragma unroll
    for (int j = 0; j < 64; j++) {
        float acc = z[j];
#pragma unroll
        for (int i = 0; i < j; i++) acc -= z[i] * Ls[j][i];
        z[j] = acc / Ls[j][j];
    }
#pragma unroll
    for (int j = 0; j < 16; j++) {
        float4 v;
        v.x = z[4 * j]; v.y = z[4 * j + 1]; v.z = z[4 * j + 2]; v.w = z[4 * j + 3];
        ((float4*)Zp)[j] = v;
    }
}

// ---------------- T = Q^T W ----------------
__global__ void k_qtw(int qi, int wi) {
    int b = blockIdx.x, t = threadIdx.x;
    __shared__ float Qs[64][65];
    __shared__ float Ws[64][65];
    const float* Q = d_Z[qi] + (size_t)b * C_ * P_;
    const float* W = d_Z[wi] + (size_t)b * C_ * P_;
    int tx = t & 15, ty = t >> 4;
    float acc[4][4] = {};
    for (int kk = 0; kk < C_; kk += 64) {
        int j = t & 63, k0 = t >> 6;
#pragma unroll
        for (int m = 0; m < 16; m++) {
            int k = k0 * 16 + m;
            Qs[k][j] = Q[(size_t)(kk + k) * P_ + j];
            Ws[k][j] = W[(size_t)(kk + k) * P_ + j];
        }
        __syncthreads();
#pragma unroll 8
        for (int k = 0; k < 64; k++) {
            float a0[4], b0[4];
#pragma unroll
            for (int u = 0; u < 4; u++) { a0[u] = Qs[k][ty * 4 + u]; b0[u] = Ws[k][tx * 4 + u]; }
#pragma unroll
            for (int u = 0; u < 4; u++)
#pragma unroll
                for (int v = 0; v < 4; v++) acc[u][v] += a0[u] * b0[v];
        }
        __syncthreads();
    }
#pragma unroll
    for (int u = 0; u < 4; u++)
#pragma unroll
        for (int v = 0; v < 4; v++)
            d_T[b * 4096 + (ty * 4 + u) * 64 + tx * 4 + v] = acc[u][v];
}

// ---------------- 64x64 symmetric Jacobi eigensolver, top-24 -> log1p(sqrt) ----------------
__global__ void k_jacobi() {
    int b = blockIdx.x, t = threadIdx.x;
    __shared__ float A[64][65];
    __shared__ float cs[32], sn[32];
    __shared__ int pi[32], pj[32];
    __shared__ float ev[64];
    const float* T = d_T + (size_t)b * 4096;
    for (int idx = t; idx < 4096; idx += 256) {
        int i = idx >> 6, j = idx & 63;
        A[i][j] = 0.5f * (T[i * 64 + j] + T[j * 64 + i]);
    }
    __syncthreads();
    for (int sw = 0; sw < 9; sw++) {
        for (int r = 0; r < 63; r++) {
            if (t < 32) {
                int i, j;
                if (t == 0) { i = 63; j = r; }
                else { i = (r + t) % 63; j = (r + 63 - t) % 63; }
                float app = A[i][i], aqq = A[j][j], apq = A[i][j];
                float c = 1.f, s = 0.f;
                if (fabsf(apq) > 1e-30f) {
                    float tau = (aqq - app) / (2.f * apq);
                    float tt = (tau >= 0.f ? 1.f : -1.f) / (fabsf(tau) + sqrtf(1.f + tau * tau));
                    c = rsqrtf(1.f + tt * tt);
                    s = tt * c;
                }
                cs[t] = c; sn[t] = s; pi[t] = i; pj[t] = j;
            }
            __syncthreads();
            for (int idx = t; idx < 2048; idx += 256) {       // A <- A J
                int p = idx >> 6, rr = idx & 63;
                int i = pi[p], j = pj[p]; float c = cs[p], s = sn[p];
                float vi = A[rr][i], vj = A[rr][j];
                A[rr][i] = c * vi - s * vj;
                A[rr][j] = s * vi + c * vj;
            }
            __syncthreads();
            for (int idx = t; idx < 2048; idx += 256) {       // A <- J^T A
                int p = idx >> 6, cc = idx & 63;
                int i = pi[p], j = pj[p]; float c = cs[p], s = sn[p];
                float vi = A[i][cc], vj = A[j][cc];
                A[i][cc] = c * vi - s * vj;
                A[j][cc] = s * vi + c * vj;
            }
            __syncthreads();
        }
    }
    if (t < 64) ev[t] = A[t][t];
    __syncthreads();
    for (int ph = 0; ph < 64; ph++) {           // odd-even sort descending
        if (t < 32) {
            int i = 2 * t + (ph & 1);
            if (i + 1 < 64) {
                float a = ev[i], c2 = ev[i + 1];
                if (a < c2) { ev[i] = c2; ev[i + 1] = a; }
            }
        }
        __syncthreads();
    }
    if (t < R_) d_svdraw[b * R_ + t] = log1pf(sqrtf(fmaxf(ev[t], 0.f)));
}

// ---------------- normalize anchors ----------------
__global__ void k_anchors(const float* __restrict__ anchors) {
    int a = blockIdx.x, t = threadIdx.x;
    __shared__ float red[32];
    float v = anchors[a * E_ + t];
    float ss = blockReduceSum(v * v, red);
    d_an[a * E_ + t] = v / fmaxf(sqrtf(ss), 1e-12f);
}

// ---------------- fused per-batch head ----------------
__global__ void k_head(const float* __restrict__ geo_state,
                       const float* __restrict__ W_svd, const float* __restrict__ b_svd,
                       const float* __restrict__ g_svd, const float* __restrict__ beta_svd,
                       const float* __restrict__ W_emb, const float* __restrict__ g_emb,
                       const float* __restrict__ beta_emb,
                       const float* __restrict__ Wc1, const float* __restrict__ bc1,
                       const float* __restrict__ Wc2, const float* __restrict__ bc2,
                       const float* __restrict__ g_c, const float* __restrict__ beta_c,
                       const float* __restrict__ W_mod, const float* __restrict__ b_mod,
                       const float* __restrict__ geo_gate,
                       const float* __restrict__ W_geo, const float* __restrict__ b_geo,
                       const float* __restrict__ g_geo, const float* __restrict__ beta_geo,
                       float* __restrict__ out) {
    int b = blockIdx.x, t = threadIdx.x;
    __shared__ float xm[C_];
    __shared__ float emb[E_];
    __shared__ float hbuf[512];
    __shared__ float pw[PW_];
    __shared__ float ctx[PW_];
    __shared__ float modin[768];
    __shared__ float cosv[A_], gate[A_];
    __shared__ float red[32];
    xm[t] = d_xmean[b * C_ + t];
    xm[t + 256] = d_xmean[b * C_ + t + 256];
    __syncthreads();
    // embedding
    {
        float acc = 0.f;
        for (int c = 0; c < C_; c++) acc += xm[c] * W_emb[c * E_ + t];
        emb[t] = acc;
        float m = blockReduceSum(acc, red) * (1.f / E_);
        float d = acc - m;
        float v = blockReduceSum(d * d, red) * (1.f / E_);
        float e2 = d * rsqrtf(v + 1e-5f) * g_emb[t] + beta_emb[t];
        float ss = blockReduceSum(e2 * e2, red);
        emb[t] = e2 / fmaxf(sqrtf(ss), 1e-12f);
    }
    __syncthreads();
    // cosines vs anchors
    {
        int a = t >> 3, l8 = t & 7;
        float acc = 0.f;
        for (int e = l8; e < E_; e += 8) acc += emb[e] * d_an[a * E_ + e];
#pragma unroll
        for (int o = 4; o; o >>= 1) acc += __shfl_xor_sync(0xffffffffu, acc, o);
        if (l8 == 0) cosv[a] = acc;
    }
    __syncthreads();
    if (t < A_) gate[t] = 0.f;
    __syncthreads();
    if (t == 0) {   // top-3 softmax gate (ties -> lower index, matching top_k)
        unsigned used = 0u;
        float tv[3]; int ti3[3];
        for (int k = 0; k < 3; k++) {
            float best = -1e30f; int bi = 0;
            for (int a = 0; a < A_; a++)
                if (!((used >> a) & 1u) && cosv[a] > best) { best = cosv[a]; bi = a; }
            used |= 1u << bi; tv[k] = best; ti3[k] = bi;
        }
        float e0 = expf(tv[0] - tv[0]), e1 = expf(tv[1] - tv[0]), e2 = expf(tv[2] - tv[0]);
        float den = e0 + e1 + e2;
        gate[ti3[0]] = e0 / den; gate[ti3[1]] = e1 / den; gate[ti3[2]] = e2 / den;
    }
    __syncthreads();
    if (t < A_) gate[t] *= (1.f - cosv[t]);   // tri_gated
    __syncthreads();
    // compartment MLP layer 1
    for (int o = t; o < 512; o += 256) {
        int nc = o >> 6, d = o & 63;
        float acc = bc1[nc * 64 + d];
        for (int a = 0; a < A_; a++) acc += gate[a] * Wc1[nc * (A_ * 64) + a * 64 + d];
        hbuf[o] = gelu_f(acc);
    }
    __syncthreads();
    // compartment MLP layer 2 + per-compartment LN (warp = compartment)
    {
        int nc = t >> 5, d = t & 31;
        float acc = bc2[nc * 32 + d];
        for (int dd = 0; dd < 64; dd++) acc += hbuf[nc * 64 + dd] * Wc2[nc * 2048 + dd * 32 + d];
        float m = acc;
#pragma unroll
        for (int o = 16; o; o >>= 1) m += __shfl_xor_sync(0xffffffffu, m, o);
        m *= (1.f / 32.f);
        float dv = acc - m, vv = dv * dv;
#pragma unroll
        for (int o = 16; o; o >>= 1) vv += __shfl_xor_sync(0xffffffffu, vv, o);
        vv *= (1.f / 32.f);
        pw[t] = dv * rsqrtf(vv + 1e-5f) * g_c[t] + beta_c[t];
    }
    __syncthreads();
    // svd context
    {
        float acc = b_svd[t];
        for (int r = 0; r < R_; r++) acc += d_svdraw[b * R_ + r] * W_svd[r * PW_ + t];
        float m = blockReduceSum(acc, red) * (1.f / PW_);
        float d = acc - m;
        float v = blockReduceSum(d * d, red) * (1.f / PW_);
        ctx[t] = gelu_f(d * rsqrtf(v + 1e-5f) * g_svd[t] + beta_svd[t]);
    }
    __syncthreads();
    modin[t] = pw[t];
    modin[256 + t] = ctx[t];
    modin[512 + t] = geo_state[b * PW_ + t];
    __syncthreads();
    // channel weights
    for (int c = t; c < C_; c += 256) {
        float acc = b_mod[c];
        for (int j = 0; j < 768; j++) acc += modin[j] * W_mod[j * C_ + c];
        d_cw[b * C_ + c] = sigm_f(acc);
    }
    // geo update
    {
        float acc = b_geo[t];
        for (int j = 0; j < PW_; j++) acc += pw[j] * W_geo[j * PW_ + t];
        float m = blockReduceSum(acc, red) * (1.f / PW_);
        float d = acc - m;
        float v = blockReduceSum(d * d, red) * (1.f / PW_);
        float ln = d * rsqrtf(v + 1e-5f) * g_geo[t] + beta_geo[t];
        float g = sigm_f(geo_gate[t]);
        out[(size_t)B_ * C_ * HW_ + b * PW_ + t] = geo_state[b * PW_ + t] + g * ln;
    }
}

// ---------------- x_out = x * cw ----------------
__global__ void k_scale(const float* __restrict__ x, float* __restrict__ out) {
    int bc = blockIdx.x;
    float w = d_cw[bc];
    const float4* xi = (const float4*)(x + (size_t)bc * HW_);
    float4* xo = (float4*)(out + (size_t)bc * HW_);
    for (int i = threadIdx.x; i < HW_ / 4; i += 256) {
        float4 v = xi[i];
        v.x *= w; v.y *= w; v.z *= w; v.w *= w;
        xo[i] = v;
    }
}

extern "C" void kernel_launch(void* const* d_in, const int* in_sizes, int n_in,
                              void* d_out, int out_size) {
    (void)in_sizes; (void)n_in; (void)out_size;
    const float* x         = (const float*)d_in[0];
    const float* geo_state = (const float*)d_in[1];
    const float* W_svd     = (const float*)d_in[2];
    const float* b_svd     = (const float*)d_in[3];
    const float* g_svd     = (const float*)d_in[4];
    const float* beta_svd  = (const float*)d_in[5];
    const float* W_emb     = (const float*)d_in[6];
    const float* g_emb     = (const float*)d_in[7];
    const float* beta_emb  = (const float*)d_in[8];
    const float* anchors   = (const float*)d_in[9];
    const float* Wc1       = (const float*)d_in[10];
    const float* bc1       = (const float*)d_in[11];
    const float* Wc2       = (const float*)d_in[12];
    const float* bc2       = (const float*)d_in[13];
    const float* g_c       = (const float*)d_in[14];
    const float* beta_c    = (const float*)d_in[15];
    const float* W_mod     = (const float*)d_in[16];
    const float* b_mod     = (const float*)d_in[17];
    const float* geo_gate  = (const float*)d_in[18];
    const float* W_geo     = (const float*)d_in[19];
    const float* b_geo     = (const float*)d_in[20];
    const float* g_geo     = (const float*)d_in[21];
    const float* beta_geo  = (const float*)d_in[22];
    float* out = (float*)d_out;

    k_colmean<<<B_ * C_, 256>>>(x);
    k_gram<<<dim3(8, 8, B_), 256>>>(x);
    k_anchors<<<A_, 256>>>(anchors);
    k_initq<<<(B_ * C_ * P_) / 256, 256>>>();

    const float cut = 2.1f;
    const float a1 = 2.f / cut, a2 = 4.f / cut;
    int qb = 0, b1 = 1, b2 = 2;
    for (int round = 0; round < 5; round++) {
        // degree-4 Chebyshev: T1=M q; T2=2M T1 - q; T3=2M T2 - T1; T4=2M T3 - T2
        k_gz<<<dim3(8, B_), 256>>>(qb, qb, b1, a1, -1.f, 0.f);
        k_gz<<<dim3(8, B_), 256>>>(b1, qb, b2, a2, -2.f, -1.f);
        k_gz<<<dim3(8, B_), 256>>>(b2, b1, b1, a2, -2.f, -1.f);
        k_gz<<<dim3(8, B_), 256>>>(b1, b2, b2, a2, -2.f, -1.f);
        k_syrk_chol<<<B_, 256>>>(b2);
        k_trsm<<<B_, 512>>>(b2);
        int tmp = qb; qb = b2; b2 = tmp;
    }
    // polish orthonormality (CholQR2 effect)
    k_syrk_chol<<<B_, 256>>>(qb);
    k_trsm<<<B_, 512>>>(qb);
    // Rayleigh-Ritz: W = G Q, T = Q^T W
    k_gz<<<dim3(8, B_), 256>>>(qb, qb, b1, 1.f, 0.f, 0.f);
    k_qtw<<<B_, 256>>>(qb, b1);
    k_jacobi<<<B_, 256>>>();

    k_head<<<B_, 256>>>(geo_state, W_svd, b_svd, g_svd, beta_svd, W_emb, g_emb, beta_emb,
                        Wc1, bc1, Wc2, bc2, g_c, beta_c, W_mod, b_mod, geo_gate,
                        W_geo, b_geo, g_geo, beta_geo, out);
    k_scale<<<B_ * C_, 256>>>(x, out);
}

// round 13
// speedup vs baseline: 1.3107x; 1.3107x over previous
#include <cuda_runtime.h>
#include <cuda_bf16.h>
#include <math.h>

#define B_   32
#define C_   512
#define HW_  1024
#define E_   256
#define A_   32
#define NC_  8
#define DC_  32
#define R_   24
#define PW_  256
#define P_   64

// ---------------- static device scratch ----------------
__device__ float d_G[B_ * C_ * C_];
__device__ float d_Z[3][B_ * C_ * P_];
__device__ float d_L[B_ * P_ * P_];
__device__ float d_T[B_ * P_ * P_];
__device__ float d_xmean[B_ * C_];
__device__ float d_an[A_ * E_];
__device__ float d_svdraw[B_ * R_];
__device__ float d_cw[B_ * C_];

// ---------------- helpers ----------------
__device__ __forceinline__ float blockReduceSum(float v, float* sh) {
    __syncthreads();
    int lane = threadIdx.x & 31, w = threadIdx.x >> 5;
#pragma unroll
    for (int o = 16; o; o >>= 1) v += __shfl_xor_sync(0xffffffffu, v, o);
    if (lane == 0) sh[w] = v;
    __syncthreads();
    int nw = blockDim.x >> 5;
    float r = (threadIdx.x < nw) ? sh[threadIdx.x] : 0.f;
    if (w == 0) {
#pragma unroll
        for (int o = 16; o; o >>= 1) r += __shfl_xor_sync(0xffffffffu, r, o);
        if (lane == 0) sh[0] = r;
    }
    __syncthreads();
    return sh[0];
}

__device__ __forceinline__ float gelu_f(float x) {
    return 0.5f * x * (1.f + erff(x * 0.70710678118654752f));
}
__device__ __forceinline__ float sigm_f(float x) { return 1.f / (1.f + expf(-x)); }

// ---------------- per-(b,c) spatial mean ----------------
__global__ void k_colmean(const float* __restrict__ x) {
    int bc = blockIdx.x;
    const float* p = x + (size_t)bc * HW_;
    float s = 0.f;
    for (int i = threadIdx.x; i < HW_; i += 256) s += p[i];
    __shared__ float red[32];
    s = blockReduceSum(s, red);
    if (threadIdx.x == 0) d_xmean[bc] = s * (1.f / HW_);
}

// ---------------- Gram: 128x128 tiles, 8x8 accumulators, lower-tri only ----------------
__global__ void __launch_bounds__(256) k_gram(const float* __restrict__ x) {
    const int TIa[10] = {0,1,1,2,2,2,3,3,3,3};
    const int TJa[10] = {0,0,1,0,1,2,0,1,2,3};
    int ti = TIa[blockIdx.x], tj = TJa[blockIdx.x], b = blockIdx.y;
    __shared__ float As[16][132];
    __shared__ float Bs[16][132];
    const float* X = x + (size_t)b * C_ * HW_;
    int t = threadIdx.x, tx = t & 15, ty = t >> 4;
    int lk = tx, li = ty;
    float acc[8][8] = {};
    for (int kk = 0; kk < HW_; kk += 16) {
#pragma unroll
        for (int m = 0; m < 8; m++) {
            int i = li + m * 16;
            As[lk][i] = X[(size_t)(ti * 128 + i) * HW_ + kk + lk];
            Bs[lk][i] = X[(size_t)(tj * 128 + i) * HW_ + kk + lk];
        }
        __syncthreads();
#pragma unroll
        for (int k = 0; k < 16; k++) {
            float a0[8], b0[8];
#pragma unroll
            for (int u = 0; u < 8; u++) { a0[u] = As[k][ty * 8 + u]; b0[u] = Bs[k][tx * 8 + u]; }
#pragma unroll
            for (int u = 0; u < 8; u++)
#pragma unroll
                for (int v = 0; v < 8; v++) acc[u][v] += a0[u] * b0[v];
        }
        __syncthreads();
    }
    float* G = d_G + (size_t)b * C_ * C_;
#pragma unroll
    for (int u = 0; u < 8; u++) {
        int gi = ti * 128 + ty * 8 + u;
        float* row = G + (size_t)gi * C_ + tj * 128 + tx * 8;
#pragma unroll
        for (int v = 0; v < 8; v++) row[v] = acc[u][v] * (1.f / HW_);
    }
}

// ---------------- mirror strictly-lower 128-blocks to upper ----------------
__global__ void k_mirror() {
    const int TIa[6] = {1,2,2,3,3,3};
    const int TJa[6] = {0,0,1,0,1,2};
    int ti = TIa[blockIdx.x], tj = TJa[blockIdx.x], b = blockIdx.y;
    __shared__ float s[32][33];
    float* G = d_G + (size_t)b * C_ * C_;
    int t = threadIdx.x, lx = t & 31, ly = t >> 5;   // ly 0..7
    for (int br = 0; br < 4; br++)
        for (int bc = 0; bc < 4; bc++) {
            int r0 = ti * 128 + br * 32, c0 = tj * 128 + bc * 32;
#pragma unroll
            for (int m = 0; m < 4; m++)
                s[ly + m * 8][lx] = G[(size_t)(r0 + ly + m * 8) * C_ + c0 + lx];
            __syncthreads();
#pragma unroll
            for (int m = 0; m < 4; m++)
                G[(size_t)(c0 + ly + m * 8) * C_ + r0 + lx] = s[lx][ly + m * 8];
            __syncthreads();
        }
}

// ---------------- deterministic pseudo-random init of Z0 ----------------
__global__ void k_initq() {
    int idx = blockIdx.x * 256 + threadIdx.x;
    unsigned int h = (unsigned int)idx * 2654435761u;
    h ^= h >> 16; h *= 2246822519u; h ^= h >> 13; h *= 3266489917u; h ^= h >> 16;
    d_Z[0][idx] = (float)(h & 0xFFFFFF) * (1.f / 8388608.f) - 1.f;
}

// ---------------- Zout = alpha*G*Zin + beta*Zin + gamma*Zprev (128x64 tiles) ----------------
__global__ void __launch_bounds__(256) k_gz(int zin, int zprev, int zout,
                                            float alpha, float beta, float gamma) {
    int rt = blockIdx.x, b = blockIdx.y;      // rt 0..3
    __shared__ float Gs[32][132];
    __shared__ float Zs[32][68];
    const float* G  = d_G + (size_t)b * C_ * C_ + (size_t)rt * 128 * C_;
    const float* Zi = d_Z[zin]  + (size_t)b * C_ * P_;
    const float* Zp = d_Z[zprev] + (size_t)b * C_ * P_;
    float*       Zo = d_Z[zout] + (size_t)b * C_ * P_;
    int t = threadIdx.x, tx = t & 15, ty = t >> 4;
    float acc[8][4] = {};
    for (int kk = 0; kk < C_; kk += 32) {
        int lk = t & 31, li = t >> 5;         // li 0..7
#pragma unroll
        for (int m = 0; m < 16; m++)
            Gs[lk][li + m * 8] = G[(size_t)(li + m * 8) * C_ + kk + lk];
        {
            int j = t & 63, k0 = t >> 6;      // k0 0..3
#pragma unroll
            for (int m = 0; m < 8; m++)
                Zs[k0 * 8 + m][j] = Zi[(size_t)(kk + k0 * 8 + m) * P_ + j];
        }
        __syncthreads();
#pragma unroll
        for (int k = 0; k < 32; k++) {
            float a0[8], b0[4];
#pragma unroll
            for (int u = 0; u < 8; u++) a0[u] = Gs[k][ty * 8 + u];
#pragma unroll
            for (int v = 0; v < 4; v++) b0[v] = Zs[k][tx * 4 + v];
#pragma unroll
            for (int u = 0; u < 8; u++)
#pragma unroll
                for (int v = 0; v < 4; v++) acc[u][v] += a0[u] * b0[v];
        }
        __syncthreads();
    }
#pragma unroll
    for (int u = 0; u < 8; u++) {
        int r = rt * 128 + ty * 8 + u;
        const float4 zi4 = *(const float4*)(Zi + (size_t)r * P_ + tx * 4);
        const float4 zp4 = *(const float4*)(Zp + (size_t)r * P_ + tx * 4);
        float4 o;
        o.x = alpha * acc[u][0] + beta * zi4.x + gamma * zp4.x;
        o.y = alpha * acc[u][1] + beta * zi4.y + gamma * zp4.y;
        o.z = alpha * acc[u][2] + beta * zi4.z + gamma * zp4.z;
        o.w = alpha * acc[u][3] + beta * zi4.w + gamma * zp4.w;
        *(float4*)(Zo + (size_t)r * P_ + tx * 4) = o;
    }
}

// ---------------- S = Z^T Z (+ridge), Cholesky -> d_L ----------------
__global__ void k_syrk_chol(int zi) {
    int b = blockIdx.x, t = threadIdx.x;
    __shared__ float Zt[64][65];
    __shared__ float S[64][65];
    __shared__ float ridge;
    const float* Z = d_Z[zi] + (size_t)b * C_ * P_;
    int tx = t & 15, ty = t >> 4;
    float acc[4][4] = {};
    for (int kk = 0; kk < C_; kk += 64) {
        int j = t & 63, k0 = t >> 6;
#pragma unroll
        for (int m = 0; m < 16; m++) {
            int k = k0 * 16 + m;
            Zt[k][j] = Z[(size_t)(kk + k) * P_ + j];
        }
        __syncthreads();
#pragma unroll 8
        for (int k = 0; k < 64; k++) {
            float a0[4], b0[4];
#pragma unroll
            for (int u = 0; u < 4; u++) { a0[u] = Zt[k][ty * 4 + u]; b0[u] = Zt[k][tx * 4 + u]; }
#pragma unroll
            for (int u = 0; u < 4; u++)
#pragma unroll
                for (int v = 0; v < 4; v++) acc[u][v] += a0[u] * b0[v];
        }
        __syncthreads();
    }
#pragma unroll
    for (int u = 0; u < 4; u++)
#pragma unroll
        for (int v = 0; v < 4; v++) S[ty * 4 + u][tx * 4 + v] = acc[u][v];
    __syncthreads();
    if (t == 0) {
        float tr = 0.f;
        for (int i = 0; i < 64; i++) tr += S[i][i];
        ridge = 1e-6f * tr * (1.f / 64.f) + 1e-18f;
    }
    __syncthreads();
    if (t < 64) S[t][t] += ridge;
    __syncthreads();
    for (int k = 0; k < 64; k++) {
        if (t == 0) S[k][k] = sqrtf(fmaxf(S[k][k], 1e-20f));
        __syncthreads();
        float dk = S[k][k];
        for (int i = k + 1 + t; i < 64; i += 256) S[i][k] /= dk;
        __syncthreads();
        int rem = 63 - k;
        for (int idx = t; idx < rem * rem; idx += 256) {
            int i = k + 1 + idx / rem, j = k + 1 + idx % rem;
            S[i][j] -= S[i][k] * S[j][k];
        }
        __syncthreads();
    }
    for (int idx = t; idx < 4096; idx += 256) d_L[b * 4096 + idx] = S[idx >> 6][idx & 63];
}

// ---------------- Z <- Z * L^{-T} (row-wise forward substitution) ----------------
__global__ void __launch_bounds__(512) k_trsm(int zi) {
    int b = blockIdx.x, t = threadIdx.x;
    __shared__ float Ls[64][65];
    for (int idx = t; idx < 4096; idx += 512) Ls[idx >> 6][idx & 63] = d_L[b * 4096 + idx];
    __syncthreads();
    float* Zp = d_Z[zi] + ((size_t)b * C_ + t) * P_;
    float z[64];
#pragma unroll
    for (int j = 0; j < 16; j++) {
        float4 v = ((const float4*)Zp)[j];
        z[4 * j] = v.x; z[4 * j + 1] = v.y; z[4 * j + 2] = v.z; z[4 * j + 3] = v.w;
    }
#pragma unroll
    for (int j = 0; j < 64; j++) {
        float acc = z[j];
#pragma unroll
        for (int i = 0; i < j; i++) acc -= z[i] * Ls[j][i];
        z[j] = acc / Ls[j][j];
    }
#pragma unroll
    for (int j = 0; j < 16; j++) {
        float4 v;
        v.x = z[4 * j]; v.y = z[4 * j + 1]; v.z = z[4 * j + 2]; v.w = z[4 * j + 3];
        ((float4*)Zp)[j] = v;
    }
}

// ---------------- T = Q^T W ----------------
__global__ void k_qtw(int qi, int wi) {
    int b = blockIdx.x, t = threadIdx.x;
    __shared__ float Qs[64][65];
    __shared__ float Ws[64][65];
    const float* Q = d_Z[qi] + (size_t)b * C_ * P_;
    const float* W = d_Z[wi] + (size_t)b * C_ * P_;
    int tx = t & 15, ty = t >> 4;
    float acc[4][4] = {};
    for (int kk = 0; kk < C_; kk += 64) {
        int j = t & 63, k0 = t >> 6;
#pragma unroll
        for (int m = 0; m < 16; m++) {
            int k = k0 * 16 + m;
            Qs[k][j] = Q[(size_t)(kk + k) * P_ + j];
            Ws[k][j] = W[(size_t)(kk + k) * P_ + j];
        }
        __syncthreads();
#pragma unroll 8
        for (int k = 0; k < 64; k++) {
            float a0[4], b0[4];
#pragma unroll
            for (int u = 0; u < 4; u++) { a0[u] = Qs[k][ty * 4 + u]; b0[u] = Ws[k][tx * 4 + u]; }
#pragma unroll
            for (int u = 0; u < 4; u++)
#pragma unroll
                for (int v = 0; v < 4; v++) acc[u][v] += a0[u] * b0[v];
        }
        __syncthreads();
    }
#pragma unroll
    for (int u = 0; u < 4; u++)
#pragma unroll
        for (int v = 0; v < 4; v++)
            d_T[b * 4096 + (ty * 4 + u) * 64 + tx * 4 + v] = acc[u][v];
}

// ---------------- 64x64 symmetric Jacobi eigensolver, top-24 -> log1p(sqrt) ----------------
__global__ void k_jacobi() {
    int b = blockIdx.x, t = threadIdx.x;
    __shared__ float A[64][65];
    __shared__ float cs[32], sn[32];
    __shared__ int pi[32], pj[32];
    __shared__ float ev[64];
    const float* T = d_T + (size_t)b * 4096;
    for (int idx = t; idx < 4096; idx += 256) {
        int i = idx >> 6, j = idx & 63;
        A[i][j] = 0.5f * (T[i * 64 + j] + T[j * 64 + i]);
    }
    __syncthreads();
    for (int sw = 0; sw < 9; sw++) {
        for (int r = 0; r < 63; r++) {
            if (t < 32) {
                int i, j;
                if (t == 0) { i = 63; j = r; }
                else { i = (r + t) % 63; j = (r + 63 - t) % 63; }
                float app = A[i][i], aqq = A[j][j], apq = A[i][j];
                float c = 1.f, s = 0.f;
                if (fabsf(apq) > 1e-30f) {
                    float tau = (aqq - app) / (2.f * apq);
                    float tt = (tau >= 0.f ? 1.f : -1.f) / (fabsf(tau) + sqrtf(1.f + tau * tau));
                    c = rsqrtf(1.f + tt * tt);
                    s = tt * c;
                }
                cs[t] = c; sn[t] = s; pi[t] = i; pj[t] = j;
            }
            __syncthreads();
            for (int idx = t; idx < 2048; idx += 256) {       // A <- A J
                int p = idx >> 6, rr = idx & 63;
                int i = pi[p], j = pj[p]; float c = cs[p], s = sn[p];
                float vi = A[rr][i], vj = A[rr][j];
                A[rr][i] = c * vi - s * vj;
                A[rr][j] = s * vi + c * vj;
            }
            __syncthreads();
            for (int idx = t; idx < 2048; idx += 256) {       // A <- J^T A
                int p = idx >> 6, cc = idx & 63;
                int i = pi[p], j = pj[p]; float c = cs[p], s = sn[p];
                float vi = A[i][cc], vj = A[j][cc];
                A[i][cc] = c * vi - s * vj;
                A[j][cc] = s * vi + c * vj;
            }
            __syncthreads();
        }
    }
    if (t < 64) ev[t] = A[t][t];
    __syncthreads();
    for (int ph = 0; ph < 64; ph++) {
        if (t < 32) {
            int i = 2 * t + (ph & 1);
            if (i + 1 < 64) {
                float a = ev[i], c2 = ev[i + 1];
                if (a < c2) { ev[i] = c2; ev[i + 1] = a; }
            }
        }
        __syncthreads();
    }
    if (t < R_) d_svdraw[b * R_ + t] = log1pf(sqrtf(fmaxf(ev[t], 0.f)));
}

// ---------------- normalize anchors ----------------
__global__ void k_anchors(const float* __restrict__ anchors) {
    int a = blockIdx.x, t = threadIdx.x;
    __shared__ float red[32];
    float v = anchors[a * E_ + t];
    float ss = blockReduceSum(v * v, red);
    d_an[a * E_ + t] = v / fmaxf(sqrtf(ss), 1e-12f);
}

// ---------------- fused per-batch head ----------------
__global__ void k_head(const float* __restrict__ geo_state,
                       const float* __restrict__ W_svd, const float* __restrict__ b_svd,
                       const float* __restrict__ g_svd, const float* __restrict__ beta_svd,
                       const float* __restrict__ W_emb, const float* __restrict__ g_emb,
                       const float* __restrict__ beta_emb,
                       const float* __restrict__ Wc1, const float* __restrict__ bc1,
                       const float* __restrict__ Wc2, const float* __restrict__ bc2,
                       const float* __restrict__ g_c, const float* __restrict__ beta_c,
                       const float* __restrict__ W_mod, const float* __restrict__ b_mod,
                       const float* __restrict__ geo_gate,
                       const float* __restrict__ W_geo, const float* __restrict__ b_geo,
                       const float* __restrict__ g_geo, const float* __restrict__ beta_geo,
                       float* __restrict__ out) {
    int b = blockIdx.x, t = threadIdx.x;
    __shared__ float xm[C_];
    __shared__ float emb[E_];
    __shared__ float hbuf[512];
    __shared__ float pw[PW_];
    __shared__ float ctx[PW_];
    __shared__ float modin[768];
    __shared__ float cosv[A_], gate[A_];
    __shared__ float red[32];
    xm[t] = d_xmean[b * C_ + t];
    xm[t + 256] = d_xmean[b * C_ + t + 256];
    __syncthreads();
    // embedding
    {
        float acc = 0.f;
        for (int c = 0; c < C_; c++) acc += xm[c] * W_emb[c * E_ + t];
        emb[t] = acc;
        float m = blockReduceSum(acc, red) * (1.f / E_);
        float d = acc - m;
        float v = blockReduceSum(d * d, red) * (1.f / E_);
        float e2 = d * rsqrtf(v + 1e-5f) * g_emb[t] + beta_emb[t];
        float ss = blockReduceSum(e2 * e2, red);
        emb[t] = e2 / fmaxf(sqrtf(ss), 1e-12f);
    }
    __syncthreads();
    // cosines vs anchors
    {
        int a = t >> 3, l8 = t & 7;
        float acc = 0.f;
        for (int e = l8; e < E_; e += 8) acc += emb[e] * d_an[a * E_ + e];
#pragma unroll
        for (int o = 4; o; o >>= 1) acc += __shfl_xor_sync(0xffffffffu, acc, o);
        if (l8 == 0) cosv[a] = acc;
    }
    __syncthreads();
    if (t < A_) gate[t] = 0.f;
    __syncthreads();
    if (t == 0) {   // top-3 softmax gate (ties -> lower index)
        unsigned used = 0u;
        float tv[3]; int ti3[3];
        for (int k = 0; k < 3; k++) {
            float best = -1e30f; int bi = 0;
            for (int a = 0; a < A_; a++)
                if (!((used >> a) & 1u) && cosv[a] > best) { best = cosv[a]; bi = a; }
            used |= 1u << bi; tv[k] = best; ti3[k] = bi;
        }
        float e0 = 1.f, e1 = expf(tv[1] - tv[0]), e2 = expf(tv[2] - tv[0]);
        float den = e0 + e1 + e2;
        gate[ti3[0]] = e0 / den; gate[ti3[1]] = e1 / den; gate[ti3[2]] = e2 / den;
    }
    __syncthreads();
    if (t < A_) gate[t] *= (1.f - cosv[t]);   // tri_gated
    __syncthreads();
    // compartment MLP layer 1
    for (int o = t; o < 512; o += 256) {
        int nc = o >> 6, d = o & 63;
        float acc = bc1[nc * 64 + d];
        for (int a = 0; a < A_; a++) acc += gate[a] * Wc1[nc * (A_ * 64) + a * 64 + d];
        hbuf[o] = gelu_f(acc);
    }
    __syncthreads();
    // compartment MLP layer 2 + per-compartment LN (warp = compartment)
    {
        int nc = t >> 5, d = t & 31;
        float acc = bc2[nc * 32 + d];
        for (int dd = 0; dd < 64; dd++) acc += hbuf[nc * 64 + dd] * Wc2[nc * 2048 + dd * 32 + d];
        float m = acc;
#pragma unroll
        for (int o = 16; o; o >>= 1) m += __shfl_xor_sync(0xffffffffu, m, o);
        m *= (1.f / 32.f);
        float dv = acc - m, vv = dv * dv;
#pragma unroll
        for (int o = 16; o; o >>= 1) vv += __shfl_xor_sync(0xffffffffu, vv, o);
        vv *= (1.f / 32.f);
        pw[t] = dv * rsqrtf(vv + 1e-5f) * g_c[t] + beta_c[t];
    }
    __syncthreads();
    // svd context
    {
        float acc = b_svd[t];
        for (int r = 0; r < R_; r++) acc += d_svdraw[b * R_ + r] * W_svd[r * PW_ + t];
        float m = blockReduceSum(acc, red) * (1.f / PW_);
        float d = acc - m;
        float v = blockReduceSum(d * d, red) * (1.f / PW_);
        ctx[t] = gelu_f(d * rsqrtf(v + 1e-5f) * g_svd[t] + beta_svd[t]);
    }
    __syncthreads();
    modin[t] = pw[t];
    modin[256 + t] = ctx[t];
    modin[512 + t] = geo_state[b * PW_ + t];
    __syncthreads();
    // channel weights
    for (int c = t; c < C_; c += 256) {
        float acc = b_mod[c];
        for (int j = 0; j < 768; j++) acc += modin[j] * W_mod[j * C_ + c];
        d_cw[b * C_ + c] = sigm_f(acc);
    }
    // geo update
    {
        float acc = b_geo[t];
        for (int j = 0; j < PW_; j++) acc += pw[j] * W_geo[j * PW_ + t];
        float m = blockReduceSum(acc, red) * (1.f / PW_);
        float d = acc - m;
        float v = blockReduceSum(d * d, red) * (1.f / PW_);
        float ln = d * rsqrtf(v + 1e-5f) * g_geo[t] + beta_geo[t];
        float g = sigm_f(geo_gate[t]);
        out[(size_t)B_ * C_ * HW_ + b * PW_ + t] = geo_state[b * PW_ + t] + g * ln;
    }
}

// ---------------- x_out = x * cw ----------------
__global__ void k_scale(const float* __restrict__ x, float* __restrict__ out) {
    int bc = blockIdx.x;
    float w = d_cw[bc];
    const float4* xi = (const float4*)(x + (size_t)bc * HW_);
    float4* xo = (float4*)(out + (size_t)bc * HW_);
    for (int i = threadIdx.x; i < HW_ / 4; i += 256) {
        float4 v = xi[i];
        v.x *= w; v.y *= w; v.z *= w; v.w *= w;
        xo[i] = v;
    }
}

extern "C" void kernel_launch(void* const* d_in, const int* in_sizes, int n_in,
                              void* d_out, int out_size) {
    (void)in_sizes; (void)n_in; (void)out_size;
    const float* x         = (const float*)d_in[0];
    const float* geo_state = (const float*)d_in[1];
    const float* W_svd     = (const float*)d_in[2];
    const float* b_svd     = (const float*)d_in[3];
    const float* g_svd     = (const float*)d_in[4];
    const float* beta_svd  = (const float*)d_in[5];
    const float* W_emb     = (const float*)d_in[6];
    const float* g_emb     = (const float*)d_in[7];
    const float* beta_emb  = (const float*)d_in[8];
    const float* anchors   = (const float*)d_in[9];
    const float* Wc1       = (const float*)d_in[10];
    const float* bc1       = (const float*)d_in[11];
    const float* Wc2       = (const float*)d_in[12];
    const float* bc2       = (const float*)d_in[13];
    const float* g_c       = (const float*)d_in[14];
    const float* beta_c    = (const float*)d_in[15];
    const float* W_mod     = (const float*)d_in[16];
    const float* b_mod     = (const float*)d_in[17];
    const float* geo_gate  = (const float*)d_in[18];
    const float* W_geo     = (const float*)d_in[19];
    const float* b_geo     = (const float*)d_in[20];
    const float* g_geo     = (const float*)d_in[21];
    const float* beta_geo  = (const float*)d_in[22];
    float* out = (float*)d_out;

    k_colmean<<<B_ * C_, 256>>>(x);
    k_gram<<<dim3(10, B_), 256>>>(x);
    k_mirror<<<dim3(6, B_), 256>>>();
    k_anchors<<<A_, 256>>>(anchors);
    k_initq<<<(B_ * C_ * P_) / 256, 256>>>();

    const float cut = 2.1f;
    const float a1 = 2.f / cut, a2 = 4.f / cut;
    int qb = 0, b1 = 1, b2 = 2;
    for (int round = 0; round < 3; round++) {
        // degree-4 Chebyshev: T1=M q; T2=2M T1 - q; T3=2M T2 - T1; T4=2M T3 - T2
        k_gz<<<dim3(4, B_), 256>>>(qb, qb, b1, a1, -1.f, 0.f);
        k_gz<<<dim3(4, B_), 256>>>(b1, qb, b2, a2, -2.f, -1.f);
        k_gz<<<dim3(4, B_), 256>>>(b2, b1, b1, a2, -2.f, -1.f);
        k_gz<<<dim3(4, B_), 256>>>(b1, b2, b2, a2, -2.f, -1.f);
        k_syrk_chol<<<B_, 256>>>(b2);
        k_trsm<<<B_, 512>>>(b2);
        int tmp = qb; qb = b2; b2 = tmp;
    }
    // polish orthonormality (CholQR2 effect)
    k_syrk_chol<<<B_, 256>>>(qb);
    k_trsm<<<B_, 512>>>(qb);
    // Rayleigh-Ritz: W = G Q, T = Q^T W
    k_gz<<<dim3(4, B_), 256>>>(qb, qb, b1, 1.f, 0.f, 0.f);
    k_qtw<<<B_, 256>>>(qb, b1);
    k_jacobi<<<B_, 256>>>();

    k_head<<<B_, 256>>>(geo_state, W_svd, b_svd, g_svd, beta_svd, W_emb, g_emb, beta_emb,
                        Wc1, bc1, Wc2, bc2, g_c, beta_c, W_mod, b_mod, geo_gate,
                        W_geo, b_geo, g_geo, beta_geo, out);
    k_scale<<<B_ * C_, 256>>>(x, out);
}

// round 14
// speedup vs baseline: 1.5978x; 1.2190x over previous
#include <cuda_runtime.h>
#include <cuda_bf16.h>
#include <math.h>

#define B_   32
#define C_   512
#define HW_  1024
#define E_   256
#define A_   32
#define NC_  8
#define DC_  32
#define R_   24
#define PW_  256
#define P_   64

// ---------------- static device scratch ----------------
__device__ float d_G[B_ * C_ * C_];
__device__ float d_Z[3][B_ * C_ * P_];
__device__ float d_L[B_ * P_ * P_];
__device__ float d_T[B_ * P_ * P_];
__device__ float d_xmean[B_ * C_];
__device__ float d_an[A_ * E_];
__device__ float d_svdraw[B_ * R_];
__device__ float d_cw[B_ * C_];
__device__ float d_modin[B_ * 768];

// ---------------- helpers ----------------
__device__ __forceinline__ float blockReduceSum(float v, float* sh) {
    __syncthreads();
    int lane = threadIdx.x & 31, w = threadIdx.x >> 5;
#pragma unroll
    for (int o = 16; o; o >>= 1) v += __shfl_xor_sync(0xffffffffu, v, o);
    if (lane == 0) sh[w] = v;
    __syncthreads();
    int nw = blockDim.x >> 5;
    float r = (threadIdx.x < nw) ? sh[threadIdx.x] : 0.f;
    if (w == 0) {
#pragma unroll
        for (int o = 16; o; o >>= 1) r += __shfl_xor_sync(0xffffffffu, r, o);
        if (lane == 0) sh[0] = r;
    }
    __syncthreads();
    return sh[0];
}

__device__ __forceinline__ float gelu_f(float x) {
    return 0.5f * x * (1.f + erff(x * 0.70710678118654752f));
}
__device__ __forceinline__ float sigm_f(float x) { return 1.f / (1.f + expf(-x)); }

// ---------------- per-(b,c) spatial mean ----------------
__global__ void k_colmean(const float* __restrict__ x) {
    int bc = blockIdx.x;
    const float* p = x + (size_t)bc * HW_;
    float s = 0.f;
    for (int i = threadIdx.x; i < HW_; i += 256) s += p[i];
    __shared__ float red[32];
    s = blockReduceSum(s, red);
    if (threadIdx.x == 0) d_xmean[bc] = s * (1.f / HW_);
}

// ---------------- Gram: 128x128 tiles, 8x8 accumulators, lower-tri only ----------------
__global__ void __launch_bounds__(256) k_gram(const float* __restrict__ x) {
    const int TIa[10] = {0,1,1,2,2,2,3,3,3,3};
    const int TJa[10] = {0,0,1,0,1,2,0,1,2,3};
    int ti = TIa[blockIdx.x], tj = TJa[blockIdx.x], b = blockIdx.y;
    __shared__ float As[16][132];
    __shared__ float Bs[16][132];
    const float* X = x + (size_t)b * C_ * HW_;
    int t = threadIdx.x, tx = t & 15, ty = t >> 4;
    int lk = tx, li = ty;
    float acc[8][8] = {};
    for (int kk = 0; kk < HW_; kk += 16) {
#pragma unroll
        for (int m = 0; m < 8; m++) {
            int i = li + m * 16;
            As[lk][i] = X[(size_t)(ti * 128 + i) * HW_ + kk + lk];
            Bs[lk][i] = X[(size_t)(tj * 128 + i) * HW_ + kk + lk];
        }
        __syncthreads();
#pragma unroll
        for (int k = 0; k < 16; k++) {
            float a0[8], b0[8];
#pragma unroll
            for (int u = 0; u < 8; u++) { a0[u] = As[k][ty * 8 + u]; b0[u] = Bs[k][tx * 8 + u]; }
#pragma unroll
            for (int u = 0; u < 8; u++)
#pragma unroll
                for (int v = 0; v < 8; v++) acc[u][v] += a0[u] * b0[v];
        }
        __syncthreads();
    }
    float* G = d_G + (size_t)b * C_ * C_;
#pragma unroll
    for (int u = 0; u < 8; u++) {
        int gi = ti * 128 + ty * 8 + u;
        float* row = G + (size_t)gi * C_ + tj * 128 + tx * 8;
#pragma unroll
        for (int v = 0; v < 8; v++) row[v] = acc[u][v] * (1.f / HW_);
    }
}

// ---------------- mirror strictly-lower 128-blocks to upper ----------------
__global__ void k_mirror() {
    const int TIa[6] = {1,2,2,3,3,3};
    const int TJa[6] = {0,0,1,0,1,2};
    int ti = TIa[blockIdx.x], tj = TJa[blockIdx.x], b = blockIdx.y;
    __shared__ float s[32][33];
    float* G = d_G + (size_t)b * C_ * C_;
    int t = threadIdx.x, lx = t & 31, ly = t >> 5;   // ly 0..7
    for (int br = 0; br < 4; br++)
        for (int bc = 0; bc < 4; bc++) {
            int r0 = ti * 128 + br * 32, c0 = tj * 128 + bc * 32;
#pragma unroll
            for (int m = 0; m < 4; m++)
                s[ly + m * 8][lx] = G[(size_t)(r0 + ly + m * 8) * C_ + c0 + lx];
            __syncthreads();
#pragma unroll
            for (int m = 0; m < 4; m++)
                G[(size_t)(c0 + ly + m * 8) * C_ + r0 + lx] = s[lx][ly + m * 8];
            __syncthreads();
        }
}

// ---------------- deterministic pseudo-random init of Z0 ----------------
__global__ void k_initq() {
    int idx = blockIdx.x * 256 + threadIdx.x;
    unsigned int h = (unsigned int)idx * 2654435761u;
    h ^= h >> 16; h *= 2246822519u; h ^= h >> 13; h *= 3266489917u; h ^= h >> 16;
    d_Z[0][idx] = (float)(h & 0xFFFFFF) * (1.f / 8388608.f) - 1.f;
}

// ---------------- Zout = alpha*G*Zin + beta*Zin + gamma*Zprev (128x64 tiles) ----------------
__global__ void __launch_bounds__(256) k_gz(int zin, int zprev, int zout,
                                            float alpha, float beta, float gamma) {
    int rt = blockIdx.x, b = blockIdx.y;      // rt 0..3
    __shared__ float Gs[32][132];
    __shared__ float Zs[32][72];              // 72-pad: rows 16B-aligned -> LDS.128
    const float* G  = d_G + (size_t)b * C_ * C_ + (size_t)rt * 128 * C_;
    const float* Zi = d_Z[zin]  + (size_t)b * C_ * P_;
    const float* Zp = d_Z[zprev] + (size_t)b * C_ * P_;
    float*       Zo = d_Z[zout] + (size_t)b * C_ * P_;
    int t = threadIdx.x, tx = t & 15, ty = t >> 4;
    float acc[8][4] = {};
    for (int kk = 0; kk < C_; kk += 32) {
        int lk = t & 31, li = t >> 5;         // li 0..7
#pragma unroll
        for (int m = 0; m < 16; m++)
            Gs[lk][li + m * 8] = G[(size_t)(li + m * 8) * C_ + kk + lk];
        {
            int j = t & 63, k0 = t >> 6;      // k0 0..3
#pragma unroll
            for (int m = 0; m < 8; m++)
                Zs[k0 * 8 + m][j] = Zi[(size_t)(kk + k0 * 8 + m) * P_ + j];
        }
        __syncthreads();
#pragma unroll
        for (int k = 0; k < 32; k++) {
            float a0[8], b0[4];
#pragma unroll
            for (int u = 0; u < 8; u++) a0[u] = Gs[k][ty * 8 + u];
#pragma unroll
            for (int v = 0; v < 4; v++) b0[v] = Zs[k][tx * 4 + v];
#pragma unroll
            for (int u = 0; u < 8; u++)
#pragma unroll
                for (int v = 0; v < 4; v++) acc[u][v] += a0[u] * b0[v];
        }
        __syncthreads();
    }
#pragma unroll
    for (int u = 0; u < 8; u++) {
        int r = rt * 128 + ty * 8 + u;
        const float4 zi4 = *(const float4*)(Zi + (size_t)r * P_ + tx * 4);
        const float4 zp4 = *(const float4*)(Zp + (size_t)r * P_ + tx * 4);
        float4 o;
        o.x = alpha * acc[u][0] + beta * zi4.x + gamma * zp4.x;
        o.y = alpha * acc[u][1] + beta * zi4.y + gamma * zp4.y;
        o.z = alpha * acc[u][2] + beta * zi4.z + gamma * zp4.z;
        o.w = alpha * acc[u][3] + beta * zi4.w + gamma * zp4.w;
        *(float4*)(Zo + (size_t)r * P_ + tx * 4) = o;
    }
}

// ---------------- S = Z^T Z (+ridge), Cholesky -> d_L ----------------
__global__ void k_syrk_chol(int zi) {
    int b = blockIdx.x, t = threadIdx.x;
    __shared__ float Zt[64][65];
    __shared__ float S[64][65];
    __shared__ float ridge;
    const float* Z = d_Z[zi] + (size_t)b * C_ * P_;
    int tx = t & 15, ty = t >> 4;
    float acc[4][4] = {};
    for (int kk = 0; kk < C_; kk += 64) {
        int j = t & 63, k0 = t >> 6;
#pragma unroll
        for (int m = 0; m < 16; m++) {
            int k = k0 * 16 + m;
            Zt[k][j] = Z[(size_t)(kk + k) * P_ + j];
        }
        __syncthreads();
#pragma unroll 8
        for (int k = 0; k < 64; k++) {
            float a0[4], b0[4];
#pragma unroll
            for (int u = 0; u < 4; u++) { a0[u] = Zt[k][ty * 4 + u]; b0[u] = Zt[k][tx * 4 + u]; }
#pragma unroll
            for (int u = 0; u < 4; u++)
#pragma unroll
                for (int v = 0; v < 4; v++) acc[u][v] += a0[u] * b0[v];
        }
        __syncthreads();
    }
#pragma unroll
    for (int u = 0; u < 4; u++)
#pragma unroll
        for (int v = 0; v < 4; v++) S[ty * 4 + u][tx * 4 + v] = acc[u][v];
    __syncthreads();
    if (t == 0) {
        float tr = 0.f;
        for (int i = 0; i < 64; i++) tr += S[i][i];
        ridge = 1e-6f * tr * (1.f / 64.f) + 1e-18f;
    }
    __syncthreads();
    if (t < 64) S[t][t] += ridge;
    __syncthreads();
    for (int k = 0; k < 64; k++) {
        if (t == 0) S[k][k] = sqrtf(fmaxf(S[k][k], 1e-20f));
        __syncthreads();
        float dk = S[k][k];
        for (int i = k + 1 + t; i < 64; i += 256) S[i][k] /= dk;
        __syncthreads();
        int rem = 63 - k;
        for (int idx = t; idx < rem * rem; idx += 256) {
            int i = k + 1 + idx / rem, j = k + 1 + idx % rem;
            S[i][j] -= S[i][k] * S[j][k];
        }
        __syncthreads();
    }
    for (int idx = t; idx < 4096; idx += 256) d_L[b * 4096 + idx] = S[idx >> 6][idx & 63];
}

// ---------------- Z <- Z * L^{-T} (row-wise forward substitution) ----------------
__global__ void __launch_bounds__(512) k_trsm(int zi) {
    int b = blockIdx.x, t = threadIdx.x;
    __shared__ float Ls[64][65];
    for (int idx = t; idx < 4096; idx += 512) Ls[idx >> 6][idx & 63] = d_L[b * 4096 + idx];
    __syncthreads();
    float* Zp = d_Z[zi] + ((size_t)b * C_ + t) * P_;
    float z[64];
#pragma unroll
    for (int j = 0; j < 16; j++) {
        float4 v = ((const float4*)Zp)[j];
        z[4 * j] = v.x; z[4 * j + 1] = v.y; z[4 * j + 2] = v.z; z[4 * j + 3] = v.w;
    }
#pragma unroll
    for (int j = 0; j < 64; j++) {
        float acc = z[j];
#pragma unroll
        for (int i = 0; i < j; i++) acc -= z[i] * Ls[j][i];
        z[j] = acc / Ls[j][j];
    }
#pragma unroll
    for (int j = 0; j < 16; j++) {
        float4 v;
        v.x = z[4 * j]; v.y = z[4 * j + 1]; v.z = z[4 * j + 2]; v.w = z[4 * j + 3];
        ((float4*)Zp)[j] = v;
    }
}

// ---------------- T = Q^T W ----------------
__global__ void k_qtw(int qi, int wi) {
    int b = blockIdx.x, t = threadIdx.x;
    __shared__ float Qs[64][65];
    __shared__ float Ws[64][65];
    const float* Q = d_Z[qi] + (size_t)b * C_ * P_;
    const float* W = d_Z[wi] + (size_t)b * C_ * P_;
    int tx = t & 15, ty = t >> 4;
    float acc[4][4] = {};
    for (int kk = 0; kk < C_; kk += 64) {
        int j = t & 63, k0 = t >> 6;
#pragma unroll
        for (int m = 0; m < 16; m++) {
            int k = k0 * 16 + m;
            Qs[k][j] = Q[(size_t)(kk + k) * P_ + j];
            Ws[k][j] = W[(size_t)(kk + k) * P_ + j];
        }
        __syncthreads();
#pragma unroll 8
        for (int k = 0; k < 64; k++) {
            float a0[4], b0[4];
#pragma unroll
            for (int u = 0; u < 4; u++) { a0[u] = Qs[k][ty * 4 + u]; b0[u] = Ws[k][tx * 4 + u]; }
#pragma unroll
            for (int u = 0; u < 4; u++)
#pragma unroll
                for (int v = 0; v < 4; v++) acc[u][v] += a0[u] * b0[v];
        }
        __syncthreads();
    }
#pragma unroll
    for (int u = 0; u < 4; u++)
#pragma unroll
        for (int v = 0; v < 4; v++)
            d_T[b * 4096 + (ty * 4 + u) * 64 + tx * 4 + v] = acc[u][v];
}

// ---------------- 64x64 symmetric Jacobi eigensolver, top-24 -> log1p(sqrt) ----------------
__global__ void k_jacobi() {
    int b = blockIdx.x, t = threadIdx.x;
    __shared__ float A[64][65];
    __shared__ float cs[32], sn[32];
    __shared__ int pi[32], pj[32];
    __shared__ float ev[64];
    const float* T = d_T + (size_t)b * 4096;
    for (int idx = t; idx < 4096; idx += 256) {
        int i = idx >> 6, j = idx & 63;
        A[i][j] = 0.5f * (T[i * 64 + j] + T[j * 64 + i]);
    }
    __syncthreads();
    for (int sw = 0; sw < 7; sw++) {
        for (int r = 0; r < 63; r++) {
            if (t < 32) {
                int i, j;
                if (t == 0) { i = 63; j = r; }
                else { i = (r + t) % 63; j = (r + 63 - t) % 63; }
                float app = A[i][i], aqq = A[j][j], apq = A[i][j];
                float c = 1.f, s = 0.f;
                if (fabsf(apq) > 1e-30f) {
                    float tau = (aqq - app) / (2.f * apq);
                    float tt = (tau >= 0.f ? 1.f : -1.f) / (fabsf(tau) + sqrtf(1.f + tau * tau));
                    c = rsqrtf(1.f + tt * tt);
                    s = tt * c;
                }
                cs[t] = c; sn[t] = s; pi[t] = i; pj[t] = j;
            }
            __syncthreads();
            for (int idx = t; idx < 2048; idx += 256) {       // A <- A J
                int p = idx >> 6, rr = idx & 63;
                int i = pi[p], j = pj[p]; float c = cs[p], s = sn[p];
                float vi = A[rr][i], vj = A[rr][j];
                A[rr][i] = c * vi - s * vj;
                A[rr][j] = s * vi + c * vj;
            }
            __syncthreads();
            for (int idx = t; idx < 2048; idx += 256) {       // A <- J^T A
                int p = idx >> 6, cc = idx & 63;
                int i = pi[p], j = pj[p]; float c = cs[p], s = sn[p];
                float vi = A[i][cc], vj = A[j][cc];
                A[i][cc] = c * vi - s * vj;
                A[j][cc] = s * vi + c * vj;
            }
            __syncthreads();
        }
    }
    if (t < 64) ev[t] = A[t][t];
    __syncthreads();
    for (int ph = 0; ph < 64; ph++) {
        if (t < 32) {
            int i = 2 * t + (ph & 1);
            if (i + 1 < 64) {
                float a = ev[i], c2 = ev[i + 1];
                if (a < c2) { ev[i] = c2; ev[i + 1] = a; }
            }
        }
        __syncthreads();
    }
    if (t < R_) d_svdraw[b * R_ + t] = log1pf(sqrtf(fmaxf(ev[t], 0.f)));
}

// ---------------- normalize anchors ----------------
__global__ void k_anchors(const float* __restrict__ anchors) {
    int a = blockIdx.x, t = threadIdx.x;
    __shared__ float red[32];
    float v = anchors[a * E_ + t];
    float ss = blockReduceSum(v * v, red);
    d_an[a * E_ + t] = v / fmaxf(sqrtf(ss), 1e-12f);
}

// ---------------- fused per-batch head (writes modin + geo_out) ----------------
__global__ void k_head(const float* __restrict__ geo_state,
                       const float* __restrict__ W_svd, const float* __restrict__ b_svd,
                       const float* __restrict__ g_svd, const float* __restrict__ beta_svd,
                       const float* __restrict__ W_emb, const float* __restrict__ g_emb,
                       const float* __restrict__ beta_emb,
                       const float* __restrict__ Wc1, const float* __restrict__ bc1,
                       const float* __restrict__ Wc2, const float* __restrict__ bc2,
                       const float* __restrict__ g_c, const float* __restrict__ beta_c,
                       const float* __restrict__ geo_gate,
                       const float* __restrict__ W_geo, const float* __restrict__ b_geo,
                       const float* __restrict__ g_geo, const float* __restrict__ beta_geo,
                       float* __restrict__ out) {
    int b = blockIdx.x, t = threadIdx.x;
    __shared__ float xm[C_];
    __shared__ float emb[E_];
    __shared__ float hbuf[512];
    __shared__ float pw[PW_];
    __shared__ float cosv[A_], gate[A_];
    __shared__ float red[32];
    xm[t] = d_xmean[b * C_ + t];
    xm[t + 256] = d_xmean[b * C_ + t + 256];
    __syncthreads();
    // embedding
    {
        float acc = 0.f;
        for (int c = 0; c < C_; c++) acc += xm[c] * W_emb[c * E_ + t];
        emb[t] = acc;
        float m = blockReduceSum(acc, red) * (1.f / E_);
        float d = acc - m;
        float v = blockReduceSum(d * d, red) * (1.f / E_);
        float e2 = d * rsqrtf(v + 1e-5f) * g_emb[t] + beta_emb[t];
        float ss = blockReduceSum(e2 * e2, red);
        emb[t] = e2 / fmaxf(sqrtf(ss), 1e-12f);
    }
    __syncthreads();
    // cosines vs anchors
    {
        int a = t >> 3, l8 = t & 7;
        float acc = 0.f;
        for (int e = l8; e < E_; e += 8) acc += emb[e] * d_an[a * E_ + e];
#pragma unroll
        for (int o = 4; o; o >>= 1) acc += __shfl_xor_sync(0xffffffffu, acc, o);
        if (l8 == 0) cosv[a] = acc;
    }
    __syncthreads();
    if (t < A_) gate[t] = 0.f;
    __syncthreads();
    if (t == 0) {   // top-3 softmax gate (ties -> lower index)
        unsigned used = 0u;
        float tv[3]; int ti3[3];
        for (int k = 0; k < 3; k++) {
            float best = -1e30f; int bi = 0;
            for (int a = 0; a < A_; a++)
                if (!((used >> a) & 1u) && cosv[a] > best) { best = cosv[a]; bi = a; }
            used |= 1u << bi; tv[k] = best; ti3[k] = bi;
        }
        float e0 = 1.f, e1 = expf(tv[1] - tv[0]), e2 = expf(tv[2] - tv[0]);
        float den = e0 + e1 + e2;
        gate[ti3[0]] = e0 / den; gate[ti3[1]] = e1 / den; gate[ti3[2]] = e2 / den;
    }
    __syncthreads();
    if (t < A_) gate[t] *= (1.f - cosv[t]);   // tri_gated
    __syncthreads();
    // compartment MLP layer 1
    for (int o = t; o < 512; o += 256) {
        int nc = o >> 6, d = o & 63;
        float acc = bc1[nc * 64 + d];
        for (int a = 0; a < A_; a++) acc += gate[a] * Wc1[nc * (A_ * 64) + a * 64 + d];
        hbuf[o] = gelu_f(acc);
    }
    __syncthreads();
    // compartment MLP layer 2 + per-compartment LN (warp = compartment)
    {
        int nc = t >> 5, d = t & 31;
        float acc = bc2[nc * 32 + d];
        for (int dd = 0; dd < 64; dd++) acc += hbuf[nc * 64 + dd] * Wc2[nc * 2048 + dd * 32 + d];
        float m = acc;
#pragma unroll
        for (int o = 16; o; o >>= 1) m += __shfl_xor_sync(0xffffffffu, m, o);
        m *= (1.f / 32.f);
        float dv = acc - m, vv = dv * dv;
#pragma unroll
        for (int o = 16; o; o >>= 1) vv += __shfl_xor_sync(0xffffffffu, vv, o);
        vv *= (1.f / 32.f);
        pw[t] = dv * rsqrtf(vv + 1e-5f) * g_c[t] + beta_c[t];
    }
    __syncthreads();
    // svd context
    float ctx_t;
    {
        float acc = b_svd[t];
        for (int r = 0; r < R_; r++) acc += d_svdraw[b * R_ + r] * W_svd[r * PW_ + t];
        float m = blockReduceSum(acc, red) * (1.f / PW_);
        float d = acc - m;
        float v = blockReduceSum(d * d, red) * (1.f / PW_);
        ctx_t = gelu_f(d * rsqrtf(v + 1e-5f) * g_svd[t] + beta_svd[t]);
    }
    // stage modulation input for k_cw
    d_modin[b * 768 + t]       = pw[t];
    d_modin[b * 768 + 256 + t] = ctx_t;
    d_modin[b * 768 + 512 + t] = geo_state[b * PW_ + t];
    // geo update
    {
        float acc = b_geo[t];
        for (int j = 0; j < PW_; j++) acc += pw[j] * W_geo[j * PW_ + t];
        float m = blockReduceSum(acc, red) * (1.f / PW_);
        float d = acc - m;
        float v = blockReduceSum(d * d, red) * (1.f / PW_);
        float ln = d * rsqrtf(v + 1e-5f) * g_geo[t] + beta_geo[t];
        float g = sigm_f(geo_gate[t]);
        out[(size_t)B_ * C_ * HW_ + b * PW_ + t] = geo_state[b * PW_ + t] + g * ln;
    }
}

// ---------------- channel weights: cw = sigmoid(modin @ W_mod + b_mod) ----------------
__global__ void k_cw(const float* __restrict__ W_mod, const float* __restrict__ b_mod) {
    int half = blockIdx.x, b = blockIdx.y;   // half 0..1 -> 256 channels each
    int t = threadIdx.x;
    __shared__ float mi[768];
    for (int i = t; i < 768; i += 256) mi[i] = d_modin[b * 768 + i];
    __syncthreads();
    int c = half * 256 + t;
    float acc = b_mod[c];
#pragma unroll 8
    for (int j = 0; j < 768; j++) acc += mi[j] * W_mod[j * C_ + c];
    d_cw[b * C_ + c] = sigm_f(acc);
}

// ---------------- x_out = x * cw ----------------
__global__ void k_scale(const float* __restrict__ x, float* __restrict__ out) {
    int bc = blockIdx.x;
    float w = d_cw[bc];
    const float4* xi = (const float4*)(x + (size_t)bc * HW_);
    float4* xo = (float4*)(out + (size_t)bc * HW_);
    for (int i = threadIdx.x; i < HW_ / 4; i += 256) {
        float4 v = xi[i];
        v.x *= w; v.y *= w; v.z *= w; v.w *= w;
        xo[i] = v;
    }
}

extern "C" void kernel_launch(void* const* d_in, const int* in_sizes, int n_in,
                              void* d_out, int out_size) {
    (void)in_sizes; (void)n_in; (void)out_size;
    const float* x         = (const float*)d_in[0];
    const float* geo_state = (const float*)d_in[1];
    const float* W_svd     = (const float*)d_in[2];
    const float* b_svd     = (const float*)d_in[3];
    const float* g_svd     = (const float*)d_in[4];
    const float* beta_svd  = (const float*)d_in[5];
    const float* W_emb     = (const float*)d_in[6];
    const float* g_emb     = (const float*)d_in[7];
    const float* beta_emb  = (const float*)d_in[8];
    const float* anchors   = (const float*)d_in[9];
    const float* Wc1       = (const float*)d_in[10];
    const float* bc1       = (const float*)d_in[11];
    const float* Wc2       = (const float*)d_in[12];
    const float* bc2       = (const float*)d_in[13];
    const float* g_c       = (const float*)d_in[14];
    const float* beta_c    = (const float*)d_in[15];
    const float* W_mod     = (const float*)d_in[16];
    const float* b_mod     = (const float*)d_in[17];
    const float* geo_gate  = (const float*)d_in[18];
    const float* W_geo     = (const float*)d_in[19];
    const float* b_geo     = (const float*)d_in[20];
    const float* g_geo     = (const float*)d_in[21];
    const float* beta_geo  = (const float*)d_in[22];
    float* out = (float*)d_out;

    k_colmean<<<B_ * C_, 256>>>(x);
    k_gram<<<dim3(10, B_), 256>>>(x);
    k_mirror<<<dim3(6, B_), 256>>>();
    k_anchors<<<A_, 256>>>(anchors);
    k_initq<<<(B_ * C_ * P_) / 256, 256>>>();

    const float cut = 2.1f;
    const float a1 = 2.f / cut, a2 = 4.f / cut;
    dim3 gz(4, B_);
    // Round A: degree-5 Chebyshev. q in Z0.
    k_gz<<<gz, 256>>>(0, 0, 1, a1, -1.f, 0.f);   // t1 = M q
    k_gz<<<gz, 256>>>(1, 0, 2, a2, -2.f, -1.f);  // t2 = 2M t1 - q
    k_gz<<<gz, 256>>>(2, 1, 0, a2, -2.f, -1.f);  // t3 = 2M t2 - t1
    k_gz<<<gz, 256>>>(0, 2, 1, a2, -2.f, -1.f);  // t4 = 2M t3 - t2
    k_gz<<<gz, 256>>>(1, 0, 2, a2, -2.f, -1.f);  // t5 = 2M t4 - t3
    k_syrk_chol<<<B_, 256>>>(2);
    k_trsm<<<B_, 512>>>(2);                      // q := Z2
    // Round B: degree-4 Chebyshev.
    k_gz<<<gz, 256>>>(2, 2, 0, a1, -1.f, 0.f);   // t1 = M q
    k_gz<<<gz, 256>>>(0, 2, 1, a2, -2.f, -1.f);  // t2 = 2M t1 - q
    k_gz<<<gz, 256>>>(1, 0, 2, a2, -2.f, -1.f);  // t3 = 2M t2 - t1
    k_gz<<<gz, 256>>>(2, 1, 0, a2, -2.f, -1.f);  // t4 = 2M t3 - t2
    k_syrk_chol<<<B_, 256>>>(0);
    k_trsm<<<B_, 512>>>(0);
    // polish orthonormality (CholQR2 effect)
    k_syrk_chol<<<B_, 256>>>(0);
    k_trsm<<<B_, 512>>>(0);
    // Rayleigh-Ritz: W = G Q, T = Q^T W
    k_gz<<<gz, 256>>>(0, 0, 1, 1.f, 0.f, 0.f);
    k_qtw<<<B_, 256>>>(0, 1);
    k_jacobi<<<B_, 256>>>();

    k_head<<<B_, 256>>>(geo_state, W_svd, b_svd, g_svd, beta_svd, W_emb, g_emb, beta_emb,
                        Wc1, bc1, Wc2, bc2, g_c, beta_c, geo_gate,
                        W_geo, b_geo, g_geo, beta_geo, out);
    k_cw<<<dim3(2, B_), 256>>>(W_mod, b_mod);
    k_scale<<<B_ * C_, 256>>>(x, out);
}